// round 11
// baseline (speedup 1.0000x reference)
#include <cuda_runtime.h>
#include <cuda_bf16.h>
#include <mma.h>
#include <math.h>
#include <stdint.h>

using namespace nvcuda;

// ---------------- problem constants ----------------
#define N_ROWS 8192
#define F_IN   512
#define H_DIM  256
#define W_DIM  64

#define RT     32                  // rows per CTA
#define NCTA   (N_ROWS / RT)       // 256
#define NTHR   256                 // 8 warps: 2 (m) x 4 (n)
#define KC     32                  // k-chunk

// smem strides (elements)
#define XS_LD  40
#define WS_LD  264
#define A_LD   264
#define W3_LD  72
#define SC_LD  264
#define SC3_LD 72

// smem offsets (bytes)
#define OFF_A2H 0
#define OFF_A2L (RT * A_LD * 2)                // 16896
#define OFF_WS  (2 * RT * A_LD * 2)            // 33792
#define WS_BUF  (KC * WS_LD * 2 * 2)           // 33792 per buffer (hi+lo)
#define WS_HI   (KC * WS_LD * 2)               // 16896
#define OFF_XS  (OFF_WS + 2 * WS_BUF)          // 101376
#define XS_HI   (RT * XS_LD * 2)               // 2560 (per-buffer hi size)
#define XS_BUF  (2 * XS_HI)                    // 5120 per buffer (hi+lo)
#define OFF_RED (OFF_XS + 2 * XS_BUF)          // 111616
#define SMEM_SZ (OFF_RED + 256)                // 111872  -> 2 CTAs/SM
#define W3_BUF  (KC * W3_LD * 2 * 2)           // 9216
#define W3_HI   (KC * W3_LD * 2)               // 4608

// ---------------- global scratch (no runtime alloc allowed) ----------------
__device__ __align__(16) __nv_bfloat16 g_W1h[F_IN * H_DIM];
__device__ __align__(16) __nv_bfloat16 g_W1l[F_IN * H_DIM];
__device__ __align__(16) __nv_bfloat16 g_W2h[H_DIM * H_DIM];
__device__ __align__(16) __nv_bfloat16 g_W2l[H_DIM * H_DIM];
__device__ __align__(16) __nv_bfloat16 g_Wqh[H_DIM * W_DIM];
__device__ __align__(16) __nv_bfloat16 g_Wql[H_DIM * W_DIM];
__device__ float g_partials[NCTA];
__device__ unsigned int g_done;      // zero-init; reset by last CTA each launch

// ---------------- helpers ----------------
__device__ __forceinline__ uint32_t smem_u32(const void* p) {
    uint32_t a;
    asm("{ .reg .u64 t; cvta.to.shared.u64 t, %1; cvt.u32.u64 %0, t; }" : "=r"(a) : "l"(p));
    return a;
}
__device__ __forceinline__ void cpa16(uint32_t s, const void* g) {
    asm volatile("cp.async.cg.shared.global [%0], [%1], 16;"
                 :: "r"(s), "l"(__cvta_generic_to_global(g)));
}
#define CP_COMMIT() asm volatile("cp.async.commit_group;" ::: "memory")
#define CP_WAIT0()  asm volatile("cp.async.wait_group 0;" ::: "memory")

// split float pair into packed bf16 hi + bf16 residual lo
__device__ __forceinline__ void split_pack(float a, float b, uint32_t& hi, uint32_t& lo) {
    __nv_bfloat16 ha = __float2bfloat16(a), hb = __float2bfloat16(b);
    float ra = a - __bfloat162float(ha), rb = b - __bfloat162float(hb);
    __nv_bfloat16 la = __float2bfloat16(ra), lb = __float2bfloat16(rb);
    hi = (uint32_t)__bfloat16_as_ushort(ha) | ((uint32_t)__bfloat16_as_ushort(hb) << 16);
    lo = (uint32_t)__bfloat16_as_ushort(la) | ((uint32_t)__bfloat16_as_ushort(lb) << 16);
}

// ---------------- prep kernel: weights fp32 -> bf16 hi/lo ----------------
#define W1P  (F_IN * H_DIM / 2)            // 65536 pairs
#define W2P  (H_DIM * H_DIM / 2)           // 32768
#define WQP  (H_DIM * W_DIM / 2)           // 8192
#define TOTP (W1P + W2P + WQP)             // 106496 = 208 * 512

__global__ void __launch_bounds__(512) prep_kernel(
    const float* __restrict__ W1, const float* __restrict__ W2,
    const float* __restrict__ Wq)
{
    unsigned i = blockIdx.x * 512u + threadIdx.x;
    const float* src; uint32_t* dh; uint32_t* dl; unsigned j;
    if (i < W1P)             { src = W1; j = i;               dh = (uint32_t*)g_W1h; dl = (uint32_t*)g_W1l; }
    else if (i < W1P + W2P)  { src = W2; j = i - W1P;         dh = (uint32_t*)g_W2h; dl = (uint32_t*)g_W2l; }
    else                     { src = Wq; j = i - W1P - W2P;   dh = (uint32_t*)g_Wqh; dl = (uint32_t*)g_Wql; }
    float2 v = reinterpret_cast<const float2*>(src)[j];
    uint32_t hi, lo; split_pack(v.x, v.y, hi, lo);
    dh[j] = hi; dl[j] = lo;
}

// ---------------- one k-step of the 3-term split GEMM ----------------
template<int MF, int NF, int LDA, int LDB>
__device__ __forceinline__ void do_kstep(
    wmma::fragment<wmma::accumulator, 16, 16, 16, float> (&acc)[MF][NF],
    const __nv_bfloat16* aH, const __nv_bfloat16* aL,
    const __nv_bfloat16* bH, const __nv_bfloat16* bL)
{
    wmma::fragment<wmma::matrix_a, 16, 16, 16, __nv_bfloat16, wmma::row_major> ah[MF], al[MF];
    wmma::fragment<wmma::matrix_b, 16, 16, 16, __nv_bfloat16, wmma::row_major> bh[NF], bl[NF];
    #pragma unroll
    for (int i = 0; i < MF; ++i) {
        wmma::load_matrix_sync(ah[i], aH + i * 16 * LDA, LDA);
        wmma::load_matrix_sync(al[i], aL + i * 16 * LDA, LDA);
    }
    #pragma unroll
    for (int j = 0; j < NF; ++j) {
        wmma::load_matrix_sync(bh[j], bH + j * 16, LDB);
        wmma::load_matrix_sync(bl[j], bL + j * 16, LDB);
    }
    #pragma unroll
    for (int i = 0; i < MF; ++i)
        #pragma unroll
        for (int j = 0; j < NF; ++j) {
            wmma::mma_sync(acc[i][j], ah[i], bh[j], acc[i][j]);
            wmma::mma_sync(acc[i][j], ah[i], bl[j], acc[i][j]);
            wmma::mma_sync(acc[i][j], al[i], bh[j], acc[i][j]);
        }
}

// ---------------- main fused MLP kernel ----------------
__global__ void __launch_bounds__(NTHR, 2) mlp_main(
    const float* __restrict__ X,
    const float* __restrict__ b1, const float* __restrict__ b2,
    const float* __restrict__ bq, const float* __restrict__ Wh,
    const float* __restrict__ bh, float* __restrict__ out)
{
    extern __shared__ char smem[];
    const uint32_t sb = smem_u32(smem);
    const int tid  = threadIdx.x;
    const int lane = tid & 31, wid = tid >> 5;
    const int wm = wid & 1, wn = wid >> 1;     // 2 (m) x 4 (n) warp grid
    const int row0 = blockIdx.x * RT;

    typedef wmma::fragment<wmma::accumulator, 16, 16, 16, float> AccFrag;

    __nv_bfloat16* a2h = (__nv_bfloat16*)(smem + OFF_A2H);
    __nv_bfloat16* a2l = (__nv_bfloat16*)(smem + OFF_A2L);

    const int xr = tid >> 3, xq = tid & 7;     // 32 rows x 8 float4-quanta (32 cols)

    // ---- staging lambdas (all 256 threads) ----
    auto stage_w1 = [&](int c, int buf) {
        int k0 = c * KC;
        #pragma unroll
        for (int it = 0; it < 4; ++it) {
            int idx = tid + it * NTHR;
            int r = idx >> 5, q = idx & 31;
            uint32_t dw = sb + OFF_WS + buf * WS_BUF + r * (WS_LD * 2) + q * 16;
            cpa16(dw,         g_W1h + (size_t)(k0 + r) * H_DIM + q * 8);
            cpa16(dw + WS_HI, g_W1l + (size_t)(k0 + r) * H_DIM + q * 8);
        }
    };
    auto stage_w2 = [&](int c, int buf) {
        int k0 = c * KC;
        #pragma unroll
        for (int it = 0; it < 4; ++it) {
            int idx = tid + it * NTHR;
            int r = idx >> 5, q = idx & 31;
            uint32_t dw = sb + OFF_WS + buf * WS_BUF + r * (WS_LD * 2) + q * 16;
            cpa16(dw,         g_W2h + (size_t)(k0 + r) * H_DIM + q * 8);
            cpa16(dw + WS_HI, g_W2l + (size_t)(k0 + r) * H_DIM + q * 8);
        }
    };
    auto stage_w3 = [&](int c, int buf) {
        int k0 = c * KC;
        int r = tid >> 3, q = tid & 7;         // 32 rows x 8 quanta (64 cols)
        uint32_t dw = sb + OFF_WS + buf * W3_BUF + r * (W3_LD * 2) + q * 16;
        cpa16(dw,         g_Wqh + (size_t)(k0 + r) * W_DIM + q * 8);
        cpa16(dw + W3_HI, g_Wql + (size_t)(k0 + r) * W_DIM + q * 8);
    };

    // ================= layer 1: C1 = X @ W1 =================
    AccFrag acc[1][4];
    #pragma unroll
    for (int j = 0; j < 4; ++j) wmma::fill_fragment(acc[0][j], 0.0f);

    float4 xreg = *reinterpret_cast<const float4*>(X + (size_t)(row0 + xr) * F_IN + xq * 4);
    stage_w1(0, 0); CP_COMMIT();

    for (int c = 0; c < F_IN / KC; ++c) {        // 16 chunks, ONE sync each
        CP_WAIT0();                               // W(c) landed (this thread)
        {   // write bf16 hi/lo X chunk c into buffer c&1
            uint32_t h0, l0, h1, l1;
            split_pack(xreg.x, xreg.y, h0, l0);
            split_pack(xreg.z, xreg.w, h1, l1);
            char* xb = smem + OFF_XS + (c & 1) * XS_BUF;
            *reinterpret_cast<uint2*>(xb +         xr * (XS_LD * 2) + xq * 8) = make_uint2(h0, h1);
            *reinterpret_cast<uint2*>(xb + XS_HI + xr * (XS_LD * 2) + xq * 8) = make_uint2(l0, l1);
        }
        __syncthreads();                          // X(c)+W(c) visible; MMA(c-1) done
        if (c < F_IN / KC - 1) {
            xreg = *reinterpret_cast<const float4*>(
                X + (size_t)(row0 + xr) * F_IN + (c + 1) * KC + xq * 4);
            stage_w1(c + 1, (c + 1) & 1); CP_COMMIT();
        }
        const __nv_bfloat16* xsh = (const __nv_bfloat16*)(smem + OFF_XS + (c & 1) * XS_BUF);
        const __nv_bfloat16* xsl = (const __nv_bfloat16*)(smem + OFF_XS + (c & 1) * XS_BUF + XS_HI);
        const __nv_bfloat16* wsH = (const __nv_bfloat16*)(smem + OFF_WS + (c & 1) * WS_BUF);
        const __nv_bfloat16* wsL = wsH + KC * WS_LD;
        #pragma unroll
        for (int ks = 0; ks < 2; ++ks)
            do_kstep<1, 4, XS_LD, WS_LD>(acc,
                xsh + wm * 16 * XS_LD + ks * 16, xsl + wm * 16 * XS_LD + ks * 16,
                wsH + ks * 16 * WS_LD + wn * 64, wsL + ks * 16 * WS_LD + wn * 64);
    }
    // epilogue 1: bias + relu + split -> A2
    {
        float* sc = (float*)(smem + OFF_WS);
        __syncthreads();                          // last MMAs done; WS free
        #pragma unroll
        for (int j = 0; j < 4; ++j)
            wmma::store_matrix_sync(sc + (wm * 16) * SC_LD + wn * 64 + j * 16,
                                    acc[0][j], SC_LD, wmma::mem_row_major);
        __syncthreads();
        int r = tid >> 3, s = tid & 7;
        #pragma unroll
        for (int j = 0; j < 32; ++j) {
            int col = s + j * 8;
            float v = fmaxf(sc[r * SC_LD + col] + __ldg(&b1[col]), 0.0f);
            __nv_bfloat16 h = __float2bfloat16(v);
            __nv_bfloat16 l = __float2bfloat16(v - __bfloat162float(h));
            a2h[r * A_LD + col] = h; a2l[r * A_LD + col] = l;
        }
        __syncthreads();
    }

    // ================= layer 2: C2 = A2 @ W2 =================
    #pragma unroll
    for (int j = 0; j < 4; ++j) wmma::fill_fragment(acc[0][j], 0.0f);

    stage_w2(0, 0); CP_COMMIT();
    for (int c = 0; c < H_DIM / KC; ++c) {       // 8 chunks
        CP_WAIT0();
        __syncthreads();
        if (c < H_DIM / KC - 1) { stage_w2(c + 1, (c + 1) & 1); CP_COMMIT(); }
        const __nv_bfloat16* wsH = (const __nv_bfloat16*)(smem + OFF_WS + (c & 1) * WS_BUF);
        const __nv_bfloat16* wsL = wsH + KC * WS_LD;
        #pragma unroll
        for (int ks = 0; ks < 2; ++ks)
            do_kstep<1, 4, A_LD, WS_LD>(acc,
                a2h + wm * 16 * A_LD + c * KC + ks * 16, a2l + wm * 16 * A_LD + c * KC + ks * 16,
                wsH + ks * 16 * WS_LD + wn * 64,         wsL + ks * 16 * WS_LD + wn * 64);
    }
    // epilogue 2: bias + relu + split -> A2 (overwrite)
    {
        float* sc = (float*)(smem + OFF_WS);
        __syncthreads();
        #pragma unroll
        for (int j = 0; j < 4; ++j)
            wmma::store_matrix_sync(sc + (wm * 16) * SC_LD + wn * 64 + j * 16,
                                    acc[0][j], SC_LD, wmma::mem_row_major);
        __syncthreads();
        int r = tid >> 3, s = tid & 7;
        #pragma unroll
        for (int j = 0; j < 32; ++j) {
            int col = s + j * 8;
            float v = fmaxf(sc[r * SC_LD + col] + __ldg(&b2[col]), 0.0f);
            __nv_bfloat16 h = __float2bfloat16(v);
            __nv_bfloat16 l = __float2bfloat16(v - __bfloat162float(h));
            a2h[r * A_LD + col] = h; a2l[r * A_LD + col] = l;
        }
        __syncthreads();
    }

    // ================= layer 3: C3 = A2 @ Wq (2m x 4n, 16x16 tiles) =================
    AccFrag acc3[1][1];
    wmma::fill_fragment(acc3[0][0], 0.0f);

    stage_w3(0, 0); CP_COMMIT();
    for (int c = 0; c < H_DIM / KC; ++c) {       // 8 chunks
        CP_WAIT0();
        __syncthreads();
        if (c < H_DIM / KC - 1) { stage_w3(c + 1, (c + 1) & 1); CP_COMMIT(); }
        const __nv_bfloat16* w3H = (const __nv_bfloat16*)(smem + OFF_WS + (c & 1) * W3_BUF);
        const __nv_bfloat16* w3L = w3H + KC * W3_LD;
        #pragma unroll
        for (int ks = 0; ks < 2; ++ks)
            do_kstep<1, 1, A_LD, W3_LD>(acc3,
                a2h + wm * 16 * A_LD + c * KC + ks * 16, a2l + wm * 16 * A_LD + c * KC + ks * 16,
                w3H + ks * 16 * W3_LD + wn * 16,         w3L + ks * 16 * W3_LD + wn * 16);
    }
    // epilogue 3: tanh + dot(Wh) + deterministic reductions
    {
        float* sc3 = (float*)(smem + OFF_WS);
        float* red = (float*)(smem + OFF_RED);
        __syncthreads();
        wmma::store_matrix_sync(sc3 + wm * 16 * SC3_LD + wn * 16,
                                acc3[0][0], SC3_LD, wmma::mem_row_major);
        __syncthreads();
        int r = tid >> 3, s = tid & 7;
        float t = 0.0f;
        #pragma unroll
        for (int j = 0; j < 8; ++j) {
            int col = s + j * 8;
            t += tanhf(sc3[r * SC3_LD + col] + __ldg(&bq[col])) * __ldg(&Wh[col]);
        }
        t += __shfl_down_sync(0xffffffffu, t, 4);
        t += __shfl_down_sync(0xffffffffu, t, 2);
        t += __shfl_down_sync(0xffffffffu, t, 1);
        if (s == 0) red[r] = t;
        __syncthreads();
        if (wid == 0) {
            float v = red[lane];                 // 32 row-partials
            #pragma unroll
            for (int sh = 16; sh > 0; sh >>= 1)
                v += __shfl_xor_sync(0xffffffffu, v, sh);
            unsigned ticket = 0;
            if (lane == 0) {
                g_partials[blockIdx.x] = v;
                __threadfence();
                ticket = atomicAdd(&g_done, 1u);
            }
            ticket = __shfl_sync(0xffffffffu, ticket, 0);
            if (ticket == NCTA - 1) {            // last CTA: final deterministic sum
                __threadfence();
                volatile float* p = g_partials;
                float tot = 0.0f;
                #pragma unroll
                for (int i = 0; i < NCTA / 32; ++i) tot += p[lane + i * 32];
                #pragma unroll
                for (int sh = 16; sh > 0; sh >>= 1)
                    tot += __shfl_xor_sync(0xffffffffu, tot, sh);
                if (lane == 0) {
                    out[0] = tot + __ldg(&bh[0]);
                    g_done = 0;                  // reset for next graph replay
                }
            }
        }
    }
}

extern "C" void kernel_launch(void* const* d_in, const int* in_sizes, int n_in,
                              void* d_out, int out_size)
{
    const float* X  = (const float*)d_in[0];
    const float* W1 = (const float*)d_in[1];
    const float* b1 = (const float*)d_in[2];
    const float* W2 = (const float*)d_in[3];
    const float* b2 = (const float*)d_in[4];
    const float* Wq = (const float*)d_in[5];
    const float* bq = (const float*)d_in[6];
    const float* Wh = (const float*)d_in[7];
    const float* bh = (const float*)d_in[8];
    float* out = (float*)d_out;

    prep_kernel<<<TOTP / 512, 512>>>(W1, W2, Wq);
    cudaFuncSetAttribute(mlp_main, cudaFuncAttributeMaxDynamicSharedMemorySize, SMEM_SZ);
    mlp_main<<<NCTA, NTHR, SMEM_SZ>>>(X, b1, b2, bq, Wh, bh, out);
}

// round 14
// speedup vs baseline: 1.2299x; 1.2299x over previous
#include <cuda_runtime.h>
#include <cuda_bf16.h>
#include <mma.h>
#include <math.h>
#include <stdint.h>

using namespace nvcuda;

// ---------------- problem constants ----------------
#define N_ROWS 8192
#define F_IN   512
#define H_DIM  256
#define W_DIM  64

#define RT     64                  // rows per CTA
#define NCTA   (N_ROWS / RT)       // 128
#define NTHR   256                 // 8 warps: 2 (m) x 4 (n)
#define KC     32                  // k-chunk
#define NC1    (F_IN / KC)         // 16
#define NC2    (H_DIM / KC)        // 8
#define NBUF   4                   // weight pipeline buffers (depth 3 in flight)

// smem strides (elements)
#define XS_LD  40
#define WS_LD  264
#define A_LD   264
#define W3_LD  72
#define SC_LD  264
#define SC3_LD 72

// smem offsets (bytes)
#define OFF_A2H 0
#define OFF_A2L (RT * A_LD * 2)                // 33792
#define OFF_WS  (2 * RT * A_LD * 2)            // 67584
#define WS_BUF  (KC * WS_LD * 2 * 2)           // 33792 per buffer (hi+lo)
#define WS_HI   (KC * WS_LD * 2)               // 16896
#define OFF_XS  (OFF_WS + NBUF * WS_BUF)       // 202752
#define XS_HI   (RT * XS_LD * 2)               // 5120
#define XS_BUF  (2 * XS_HI)                    // 10240 per buffer (hi+lo)
#define OFF_RED (OFF_XS + 2 * XS_BUF)          // 223232
#define SMEM_SZ (OFF_RED + 256)                // 223488 (1 CTA/SM)
#define W3_HI_SZ (H_DIM * W3_LD * 2)           // 36864 (full Wq hi)

// ---------------- global scratch ----------------
__device__ __align__(16) __nv_bfloat16 g_W1h[F_IN * H_DIM];
__device__ __align__(16) __nv_bfloat16 g_W1l[F_IN * H_DIM];
__device__ __align__(16) __nv_bfloat16 g_W2h[H_DIM * H_DIM];
__device__ __align__(16) __nv_bfloat16 g_W2l[H_DIM * H_DIM];
__device__ __align__(16) __nv_bfloat16 g_Wqh[H_DIM * W_DIM];
__device__ __align__(16) __nv_bfloat16 g_Wql[H_DIM * W_DIM];
__device__ float g_partials[NCTA];
__device__ unsigned int g_done;      // zero-init; reset by last CTA each launch

// ---------------- helpers ----------------
__device__ __forceinline__ uint32_t smem_u32(const void* p) {
    uint32_t a;
    asm("{ .reg .u64 t; cvta.to.shared.u64 t, %1; cvt.u32.u64 %0, t; }" : "=r"(a) : "l"(p));
    return a;
}
__device__ __forceinline__ void cpa16(uint32_t s, const void* g) {
    asm volatile("cp.async.cg.shared.global [%0], [%1], 16;"
                 :: "r"(s), "l"(__cvta_generic_to_global(g)));
}
#define CP_COMMIT() asm volatile("cp.async.commit_group;" ::: "memory")
#define CP_WAIT2()  asm volatile("cp.async.wait_group 2;" ::: "memory")
#define CP_WAIT0()  asm volatile("cp.async.wait_group 0;" ::: "memory")

// split float pair into packed bf16 hi + bf16 residual lo
__device__ __forceinline__ void split_pack(float a, float b, uint32_t& hi, uint32_t& lo) {
    __nv_bfloat16 ha = __float2bfloat16(a), hb = __float2bfloat16(b);
    float ra = a - __bfloat162float(ha), rb = b - __bfloat162float(hb);
    __nv_bfloat16 la = __float2bfloat16(ra), lb = __float2bfloat16(rb);
    hi = (uint32_t)__bfloat16_as_ushort(ha) | ((uint32_t)__bfloat16_as_ushort(hb) << 16);
    lo = (uint32_t)__bfloat16_as_ushort(la) | ((uint32_t)__bfloat16_as_ushort(lb) << 16);
}

// ---------------- prep kernel: weights fp32 -> bf16 hi/lo ----------------
#define W1P  (F_IN * H_DIM / 2)            // 65536 pairs
#define W2P  (H_DIM * H_DIM / 2)           // 32768
#define WQP  (H_DIM * W_DIM / 2)           // 8192
#define TOTP (W1P + W2P + WQP)             // 106496 = 208 * 512

__global__ void __launch_bounds__(512) prep_kernel(
    const float* __restrict__ W1, const float* __restrict__ W2,
    const float* __restrict__ Wq)
{
    unsigned i = blockIdx.x * 512u + threadIdx.x;
    const float* src; uint32_t* dh; uint32_t* dl; unsigned j;
    if (i < W1P)             { src = W1; j = i;               dh = (uint32_t*)g_W1h; dl = (uint32_t*)g_W1l; }
    else if (i < W1P + W2P)  { src = W2; j = i - W1P;         dh = (uint32_t*)g_W2h; dl = (uint32_t*)g_W2l; }
    else                     { src = Wq; j = i - W1P - W2P;   dh = (uint32_t*)g_Wqh; dl = (uint32_t*)g_Wql; }
    float2 v = reinterpret_cast<const float2*>(src)[j];
    uint32_t hi, lo; split_pack(v.x, v.y, hi, lo);
    dh[j] = hi; dl[j] = lo;
}

// ---------------- one k-step of the 3-term split GEMM ----------------
template<int MF, int NF, int LDA, int LDB>
__device__ __forceinline__ void do_kstep(
    wmma::fragment<wmma::accumulator, 16, 16, 16, float> (&acc)[MF][NF],
    const __nv_bfloat16* aH, const __nv_bfloat16* aL,
    const __nv_bfloat16* bH, const __nv_bfloat16* bL)
{
    wmma::fragment<wmma::matrix_a, 16, 16, 16, __nv_bfloat16, wmma::row_major> ah[MF], al[MF];
    wmma::fragment<wmma::matrix_b, 16, 16, 16, __nv_bfloat16, wmma::row_major> bh[NF], bl[NF];
    #pragma unroll
    for (int i = 0; i < MF; ++i) {
        wmma::load_matrix_sync(ah[i], aH + i * 16 * LDA, LDA);
        wmma::load_matrix_sync(al[i], aL + i * 16 * LDA, LDA);
    }
    #pragma unroll
    for (int j = 0; j < NF; ++j) {
        wmma::load_matrix_sync(bh[j], bH + j * 16, LDB);
        wmma::load_matrix_sync(bl[j], bL + j * 16, LDB);
    }
    #pragma unroll
    for (int i = 0; i < MF; ++i)
        #pragma unroll
        for (int j = 0; j < NF; ++j) {
            wmma::mma_sync(acc[i][j], ah[i], bh[j], acc[i][j]);
            wmma::mma_sync(acc[i][j], ah[i], bl[j], acc[i][j]);
            wmma::mma_sync(acc[i][j], al[i], bh[j], acc[i][j]);
        }
}

// ---------------- main fused MLP kernel ----------------
__global__ void __launch_bounds__(NTHR) mlp_main(
    const float* __restrict__ X,
    const float* __restrict__ b1, const float* __restrict__ b2,
    const float* __restrict__ bq, const float* __restrict__ Wh,
    const float* __restrict__ bh, float* __restrict__ out)
{
    extern __shared__ char smem[];
    const uint32_t sb = smem_u32(smem);
    const int tid  = threadIdx.x;
    const int lane = tid & 31, wid = tid >> 5;
    const int wm = wid & 1, wn = wid >> 1;     // 2 (m) x 4 (n) warp grid
    const int row0 = blockIdx.x * RT;

    typedef wmma::fragment<wmma::accumulator, 16, 16, 16, float> AccFrag;

    __nv_bfloat16* a2h = (__nv_bfloat16*)(smem + OFF_A2H);
    __nv_bfloat16* a2l = (__nv_bfloat16*)(smem + OFF_A2L);

    // ---- staging helpers (all 256 threads) ----
    auto stage_w = [&](const __nv_bfloat16* gh, const __nv_bfloat16* gl, int c, int buf) {
        int k0 = c * KC;
        #pragma unroll
        for (int it = 0; it < 4; ++it) {
            int idx = tid + it * NTHR;
            int r = idx >> 5, q = idx & 31;
            uint32_t dw = sb + OFF_WS + buf * WS_BUF + r * (WS_LD * 2) + q * 16;
            cpa16(dw,         gh + (size_t)(k0 + r) * H_DIM + q * 8);
            cpa16(dw + WS_HI, gl + (size_t)(k0 + r) * H_DIM + q * 8);
        }
    };

    // X chunk handling: 64 rows x 32 cols; 512 float4 slots, 2 per thread
    const int xr0 = tid >> 3,        xq0 = tid & 7;
    const int xr1 = (tid + 256) >> 3, xq1 = (tid + 256) & 7;
    float4 xa, xb;
    auto loadX = [&](int c) {
        xa = *reinterpret_cast<const float4*>(X + (size_t)(row0 + xr0) * F_IN + c * KC + xq0 * 4);
        xb = *reinterpret_cast<const float4*>(X + (size_t)(row0 + xr1) * F_IN + c * KC + xq1 * 4);
    };
    auto storeX = [&](int c) {
        char* xbuf = smem + OFF_XS + (c & 1) * XS_BUF;
        uint32_t h0, l0, h1, l1;
        split_pack(xa.x, xa.y, h0, l0); split_pack(xa.z, xa.w, h1, l1);
        *reinterpret_cast<uint2*>(xbuf +         xr0 * (XS_LD * 2) + xq0 * 8) = make_uint2(h0, h1);
        *reinterpret_cast<uint2*>(xbuf + XS_HI + xr0 * (XS_LD * 2) + xq0 * 8) = make_uint2(l0, l1);
        split_pack(xb.x, xb.y, h0, l0); split_pack(xb.z, xb.w, h1, l1);
        *reinterpret_cast<uint2*>(xbuf +         xr1 * (XS_LD * 2) + xq1 * 8) = make_uint2(h0, h1);
        *reinterpret_cast<uint2*>(xbuf + XS_HI + xr1 * (XS_LD * 2) + xq1 * 8) = make_uint2(l0, l1);
    };

    // ================= layer 1: C1 = X @ W1 =================
    AccFrag acc[2][4];
    #pragma unroll
    for (int i = 0; i < 2; ++i)
        #pragma unroll
        for (int j = 0; j < 4; ++j) wmma::fill_fragment(acc[i][j], 0.0f);

    loadX(0);
    stage_w(g_W1h, g_W1l, 0, 0); CP_COMMIT();
    stage_w(g_W1h, g_W1l, 1, 1); CP_COMMIT();
    stage_w(g_W1h, g_W1l, 2, 2); CP_COMMIT();

    for (int c = 0; c < NC1; ++c) {
        CP_WAIT2();                    // group c complete (this thread)
        storeX(c);
        __syncthreads();               // X(c)+W(c) visible; MMA(c-1) done by all
        if (c < NC1 - 1) loadX(c + 1);
        if (c + 3 < NC1) stage_w(g_W1h, g_W1l, c + 3, (c + 3) & 3);
        CP_COMMIT();                   // empty group when nothing staged
        const __nv_bfloat16* xsh = (const __nv_bfloat16*)(smem + OFF_XS + (c & 1) * XS_BUF);
        const __nv_bfloat16* xsl = (const __nv_bfloat16*)(smem + OFF_XS + (c & 1) * XS_BUF + XS_HI);
        const __nv_bfloat16* wsH = (const __nv_bfloat16*)(smem + OFF_WS + (c & 3) * WS_BUF);
        const __nv_bfloat16* wsL = wsH + KC * WS_LD;
        #pragma unroll
        for (int ks = 0; ks < 2; ++ks)
            do_kstep<2, 4, XS_LD, WS_LD>(acc,
                xsh + wm * 32 * XS_LD + ks * 16, xsl + wm * 32 * XS_LD + ks * 16,
                wsH + ks * 16 * WS_LD + wn * 64, wsL + ks * 16 * WS_LD + wn * 64);
    }
    // epilogue 1: bias + relu + split -> A2
    {
        float* sc = (float*)(smem + OFF_WS);
        __syncthreads();               // all MMA(NC1-1) done; WS free
        #pragma unroll
        for (int i = 0; i < 2; ++i)
            #pragma unroll
            for (int j = 0; j < 4; ++j)
                wmma::store_matrix_sync(sc + (wm * 32 + i * 16) * SC_LD + wn * 64 + j * 16,
                                        acc[i][j], SC_LD, wmma::mem_row_major);
        __syncthreads();
        int r = tid >> 2, s = tid & 3;
        #pragma unroll
        for (int j = 0; j < 64; ++j) {
            int col = s + j * 4;
            float v = fmaxf(sc[r * SC_LD + col] + __ldg(&b1[col]), 0.0f);
            __nv_bfloat16 h = __float2bfloat16(v);
            __nv_bfloat16 l = __float2bfloat16(v - __bfloat162float(h));
            a2h[r * A_LD + col] = h; a2l[r * A_LD + col] = l;
        }
        __syncthreads();
    }

    // ================= layer 2: C2 = A2 @ W2 =================
    #pragma unroll
    for (int i = 0; i < 2; ++i)
        #pragma unroll
        for (int j = 0; j < 4; ++j) wmma::fill_fragment(acc[i][j], 0.0f);

    stage_w(g_W2h, g_W2l, 0, 0); CP_COMMIT();
    stage_w(g_W2h, g_W2l, 1, 1); CP_COMMIT();
    stage_w(g_W2h, g_W2l, 2, 2); CP_COMMIT();

    for (int c = 0; c < NC2; ++c) {
        CP_WAIT2();
        __syncthreads();
        if (c + 3 < NC2) stage_w(g_W2h, g_W2l, c + 3, (c + 3) & 3);
        CP_COMMIT();
        const __nv_bfloat16* wsH = (const __nv_bfloat16*)(smem + OFF_WS + (c & 3) * WS_BUF);
        const __nv_bfloat16* wsL = wsH + KC * WS_LD;
        #pragma unroll
        for (int ks = 0; ks < 2; ++ks)
            do_kstep<2, 4, A_LD, WS_LD>(acc,
                a2h + wm * 32 * A_LD + c * KC + ks * 16, a2l + wm * 32 * A_LD + c * KC + ks * 16,
                wsH + ks * 16 * WS_LD + wn * 64,         wsL + ks * 16 * WS_LD + wn * 64);
    }
    // epilogue 2: bias + relu + split -> A2 (overwrite)
    {
        float* sc = (float*)(smem + OFF_WS);
        __syncthreads();
        #pragma unroll
        for (int i = 0; i < 2; ++i)
            #pragma unroll
            for (int j = 0; j < 4; ++j)
                wmma::store_matrix_sync(sc + (wm * 32 + i * 16) * SC_LD + wn * 64 + j * 16,
                                        acc[i][j], SC_LD, wmma::mem_row_major);
        __syncthreads();
        int r = tid >> 2, s = tid & 3;
        #pragma unroll
        for (int j = 0; j < 64; ++j) {
            int col = s + j * 4;
            float v = fmaxf(sc[r * SC_LD + col] + __ldg(&b2[col]), 0.0f);
            __nv_bfloat16 h = __float2bfloat16(v);
            __nv_bfloat16 l = __float2bfloat16(v - __bfloat162float(h));
            a2h[r * A_LD + col] = h; a2l[r * A_LD + col] = l;
        }
        __syncthreads();
    }

    // ================= layer 3: C3 = A2 @ Wq (whole Wq resident) =================
    // stage full Wq hi+lo: 256 k-rows x 64 cols, row stride W3_LD
    {
        #pragma unroll
        for (int it = 0; it < 8; ++it) {
            int idx = tid + it * NTHR;         // 2048 quanta
            int r = idx >> 3, q = idx & 7;
            uint32_t dw = sb + OFF_WS + r * (W3_LD * 2) + q * 16;
            cpa16(dw,            g_Wqh + (size_t)r * W_DIM + q * 8);
            cpa16(dw + W3_HI_SZ, g_Wql + (size_t)r * W_DIM + q * 8);
        }
        CP_COMMIT(); CP_WAIT0();
        __syncthreads();
    }
    AccFrag acc3[2][1];
    wmma::fill_fragment(acc3[0][0], 0.0f);
    wmma::fill_fragment(acc3[1][0], 0.0f);
    {
        const __nv_bfloat16* w3H = (const __nv_bfloat16*)(smem + OFF_WS);
        const __nv_bfloat16* w3L = (const __nv_bfloat16*)(smem + OFF_WS + W3_HI_SZ);
        #pragma unroll 4
        for (int kt = 0; kt < H_DIM / 16; ++kt)      // 16 k-tiles, zero syncs
            do_kstep<2, 1, A_LD, W3_LD>(acc3,
                a2h + wm * 32 * A_LD + kt * 16, a2l + wm * 32 * A_LD + kt * 16,
                w3H + kt * 16 * W3_LD + wn * 16, w3L + kt * 16 * W3_LD + wn * 16);
    }
    // epilogue 3: tanh + dot(Wh) + deterministic reductions
    {
        float* sc3 = (float*)(smem + OFF_WS);
        float* red = (float*)(smem + OFF_RED);
        __syncthreads();               // W3 reads done
        #pragma unroll
        for (int i = 0; i < 2; ++i)
            wmma::store_matrix_sync(sc3 + (wm * 32 + i * 16) * SC3_LD + wn * 16,
                                    acc3[i][0], SC3_LD, wmma::mem_row_major);
        __syncthreads();
        int r = tid >> 2, s = tid & 3;
        float t = 0.0f;
        #pragma unroll
        for (int j = 0; j < 16; ++j) {
            int col = s + j * 4;
            t += tanhf(sc3[r * SC3_LD + col] + __ldg(&bq[col])) * __ldg(&Wh[col]);
        }
        t += __shfl_down_sync(0xffffffffu, t, 2);
        t += __shfl_down_sync(0xffffffffu, t, 1);
        if (s == 0) red[r] = t;        // 64 row partials
        __syncthreads();
        if (wid == 0) {
            float v = red[lane] + red[lane + 32];
            #pragma unroll
            for (int sh = 16; sh > 0; sh >>= 1)
                v += __shfl_xor_sync(0xffffffffu, v, sh);
            unsigned ticket = 0;
            if (lane == 0) {
                g_partials[blockIdx.x] = v;
                __threadfence();
                ticket = atomicAdd(&g_done, 1u);
            }
            ticket = __shfl_sync(0xffffffffu, ticket, 0);
            if (ticket == NCTA - 1) {  // last CTA: deterministic final sum
                __threadfence();
                volatile float* p = g_partials;
                float tot = (p[lane] + p[lane + 32]) + (p[lane + 64] + p[lane + 96]);
                #pragma unroll
                for (int sh = 16; sh > 0; sh >>= 1)
                    tot += __shfl_xor_sync(0xffffffffu, tot, sh);
                if (lane == 0) {
                    out[0] = tot + __ldg(&bh[0]);
                    g_done = 0;        // reset for next graph replay
                }
            }
        }
    }
}

extern "C" void kernel_launch(void* const* d_in, const int* in_sizes, int n_in,
                              void* d_out, int out_size)
{
    const float* X  = (const float*)d_in[0];
    const float* W1 = (const float*)d_in[1];
    const float* b1 = (const float*)d_in[2];
    const float* W2 = (const float*)d_in[3];
    const float* b2 = (const float*)d_in[4];
    const float* Wq = (const float*)d_in[5];
    const float* bq = (const float*)d_in[6];
    const float* Wh = (const float*)d_in[7];
    const float* bh = (const float*)d_in[8];
    float* out = (float*)d_out;

    prep_kernel<<<TOTP / 512, 512>>>(W1, W2, Wq);
    cudaFuncSetAttribute(mlp_main, cudaFuncAttributeMaxDynamicSharedMemorySize, SMEM_SZ);
    mlp_main<<<NCTA, NTHR, SMEM_SZ>>>(X, b1, b2, bq, Wh, bh, out);
}